// round 13
// baseline (speedup 1.0000x reference)
#include <cuda_runtime.h>
#include <math.h>

// Problem constants
#define BB 8
#define NN 128
#define HN_ 256
#define HE_ 128
#define NH 8
#define DH_ 32
#define PP 8128
#define BP 65024   // B * P

typedef unsigned long long ull;

__device__ __forceinline__ ull pk2(float x, float y) {
    ull r; asm("mov.b64 %0,{%1,%2};" : "=l"(r) : "f"(x), "f"(y)); return r;
}
__device__ __forceinline__ float2 upk2(ull v) {
    float2 f; asm("mov.b64 {%0,%1},%2;" : "=f"(f.x), "=f"(f.y) : "l"(v)); return f;
}
// d = a*b + d  (packed f32x2 FFMA) — only where operands are pre-packed (k_lsm)
__device__ __forceinline__ void fma2(ull& d, ull a, ull b) {
    asm("fma.rn.f32x2 %0,%1,%2,%0;" : "+l"(d) : "l"(a), "l"(b));
}

// Scratch (no cudaMalloc allowed -> __device__ globals)
__device__ float g_n_in[1024 * 256];     // [B*N, HN]
__device__ float g_qkv[1024 * 768];      // [B*N, 3*HN]
__device__ float g_e_in[BP * 128];       // [B*P, HE]
__device__ float g_att[64 * 128 * 128];  // [B*H, N, N] adj -> probs (in place)
__device__ float g_anyv[1024];           // [B*N]
__device__ float g_attn[1024 * 256];     // [B*N, HN]

__device__ __forceinline__ int pair_idx(int i, int j) {
    if (i > j) { int t = i; i = j; j = t; }
    return i * (255 - i) / 2 + (j - i - 1);
}

// ---------------------------------------------------------------------------
// K1: FUSED node LayerNorm + qkv GEMM.  grid=(64,3), block=256.
// Each block stages 16 raw node rows, LayerNorms them in smem (redundantly
// across the 3 column-blocks; y==0 also writes g_n_in for k_out), then GEMMs.
// ---------------------------------------------------------------------------
__global__ void k_qkv(const float* __restrict__ nf,
                      const float* __restrict__ gn, const float* __restrict__ bn,
                      const float* __restrict__ W, const float* __restrict__ bias) {
    __shared__ float As[16 * 256];
    __shared__ float gns[256], bns[256];
    int t = threadIdx.x;
    int row0 = blockIdx.x * 16;
    int cb = blockIdx.y * 256;
    const float4* a4 = (const float4*)(nf + (size_t)row0 * 256);
    float4* s4 = (float4*)As;
    #pragma unroll
    for (int i = t; i < 1024; i += 256) s4[i] = a4[i];
    gns[t] = gn[t];
    bns[t] = bn[t];
    __syncthreads();

    // LayerNorm 16 rows: warp w handles rows w*2, w*2+1; lane owns 8 cols.
    {
        int w = t >> 5, l = t & 31;
        #pragma unroll
        for (int rr = 0; rr < 2; rr++) {
            int r = w * 2 + rr;
            int c = l * 8;
            float4 v0 = *(float4*)&As[r * 256 + c];
            float4 v1 = *(float4*)&As[r * 256 + c + 4];
            float s  = v0.x + v0.y + v0.z + v0.w + v1.x + v1.y + v1.z + v1.w;
            float s2 = v0.x * v0.x + v0.y * v0.y + v0.z * v0.z + v0.w * v0.w
                     + v1.x * v1.x + v1.y * v1.y + v1.z * v1.z + v1.w * v1.w;
            #pragma unroll
            for (int o = 16; o; o >>= 1) {
                s  += __shfl_xor_sync(0xFFFFFFFFu, s,  o);
                s2 += __shfl_xor_sync(0xFFFFFFFFu, s2, o);
            }
            float mean = s * (1.0f / 256.0f);
            float var  = s2 * (1.0f / 256.0f) - mean * mean;
            float rstd = rsqrtf(var + 1e-5f);
            float4 o0, o1;
            o0.x = (v0.x - mean) * rstd * gns[c + 0] + bns[c + 0];
            o0.y = (v0.y - mean) * rstd * gns[c + 1] + bns[c + 1];
            o0.z = (v0.z - mean) * rstd * gns[c + 2] + bns[c + 2];
            o0.w = (v0.w - mean) * rstd * gns[c + 3] + bns[c + 3];
            o1.x = (v1.x - mean) * rstd * gns[c + 4] + bns[c + 4];
            o1.y = (v1.y - mean) * rstd * gns[c + 5] + bns[c + 5];
            o1.z = (v1.z - mean) * rstd * gns[c + 6] + bns[c + 6];
            o1.w = (v1.w - mean) * rstd * gns[c + 7] + bns[c + 7];
            *(float4*)&As[r * 256 + c] = o0;
            *(float4*)&As[r * 256 + c + 4] = o1;
        }
    }
    __syncthreads();

    if (blockIdx.y == 0) {   // persist n_in for k_out
        float4* dst = (float4*)(g_n_in + (size_t)row0 * 256);
        #pragma unroll
        for (int i = t; i < 1024; i += 256) dst[i] = s4[i];
    }

    int cg = t & 63;
    int rg = t >> 6;
    float4 acc[4];
    #pragma unroll
    for (int r = 0; r < 4; r++) acc[r] = make_float4(0.f, 0.f, 0.f, 0.f);
    for (int k = 0; k < 256; k++) {
        float4 w = *(const float4*)&W[k * 768 + cb + cg * 4];
        #pragma unroll
        for (int r = 0; r < 4; r++) {
            float a = As[(rg * 4 + r) * 256 + k];
            acc[r].x += a * w.x; acc[r].y += a * w.y;
            acc[r].z += a * w.z; acc[r].w += a * w.w;
        }
    }
    float4 bb = *(const float4*)&bias[cb + cg * 4];
    #pragma unroll
    for (int r = 0; r < 4; r++) {
        float4 o;
        o.x = acc[r].x + bb.x; o.y = acc[r].y + bb.y;
        o.z = acc[r].z + bb.z; o.w = acc[r].w + bb.w;
        *(float4*)&g_qkv[(row0 + rg * 4 + r) * 768 + cb + cg * 4] = o;
    }
}

// ---------------------------------------------------------------------------
// K3: edge LayerNorm + e_adj scatter into g_att.  [R8/R12 — unchanged]
// grid = 1016 (64 edge rows per block), block = 256.
// ---------------------------------------------------------------------------
__global__ void k_edge(const float* __restrict__ ef,
                       const float* __restrict__ ge, const float* __restrict__ be,
                       const float* __restrict__ Wea, const float* __restrict__ bea,
                       const int* __restrict__ i1, const int* __restrict__ i2,
                       const float* __restrict__ mask) {
    __shared__ float es[64 * 132];
    __shared__ float wa[128 * 8];
    __shared__ float ges[128], bes[128];
    __shared__ int s_i[64], s_j[64];
    __shared__ float s_mask[64];
    int t = threadIdx.x;
    int base_row = blockIdx.x * 64;
    int b = base_row / 8128;
    int p0 = base_row - b * 8128;
    int base = base_row * 128;

    float4* es4 = (float4*)es;
    const float4* ef4 = (const float4*)(ef + base);
    #pragma unroll
    for (int i = t; i < 2048; i += 256) es4[(i >> 5) * 33 + (i & 31)] = ef4[i];
    for (int i = t; i < 1024; i += 256) wa[i] = Wea[i];
    if (t < 128) { ges[t] = ge[t]; bes[t] = be[t]; }
    if (t < 64) {
        int p = p0 + t;
        s_i[t] = i1[p]; s_j[t] = i2[p];
        s_mask[t] = mask[b * PP + p];
    }
    __syncthreads();

    int w = t >> 5, l = t & 31;
    #pragma unroll
    for (int rr = 0; rr < 8; rr++) {
        int r = w * 8 + rr;
        float4 v = *(float4*)&es[r * 132 + l * 4];
        float s  = v.x + v.y + v.z + v.w;
        float s2 = v.x * v.x + v.y * v.y + v.z * v.z + v.w * v.w;
        #pragma unroll
        for (int o = 16; o; o >>= 1) {
            s  += __shfl_xor_sync(0xFFFFFFFFu, s,  o);
            s2 += __shfl_xor_sync(0xFFFFFFFFu, s2, o);
        }
        float mean = s * (1.0f / 128.0f);
        float var  = s2 * (1.0f / 128.0f) - mean * mean;
        float rstd = rsqrtf(var + 1e-5f);
        int c = l * 4;
        float4 o4;
        o4.x = (v.x - mean) * rstd * ges[c + 0] + bes[c + 0];
        o4.y = (v.y - mean) * rstd * ges[c + 1] + bes[c + 1];
        o4.z = (v.z - mean) * rstd * ges[c + 2] + bes[c + 2];
        o4.w = (v.w - mean) * rstd * ges[c + 3] + bes[c + 3];
        *(float4*)&es[r * 132 + c] = o4;
    }
    __syncthreads();

    float4* out4 = (float4*)(g_e_in + base);
    #pragma unroll
    for (int i = t; i < 2048; i += 256) out4[i] = es4[(i >> 5) * 33 + (i & 31)];

    {
        int r = t >> 2, q = t & 3;
        float s0 = 0.f, s1 = 0.f;
        #pragma unroll 8
        for (int c4 = 0; c4 < 32; c4++) {
            float4 e4 = *(float4*)&es[r * 132 + c4 * 4];
            int c = c4 * 4;
            float2 w0 = *(float2*)&wa[(c + 0) * 8 + q * 2];
            float2 w1 = *(float2*)&wa[(c + 1) * 8 + q * 2];
            float2 w2 = *(float2*)&wa[(c + 2) * 8 + q * 2];
            float2 w3 = *(float2*)&wa[(c + 3) * 8 + q * 2];
            s0 += e4.x * w0.x + e4.y * w1.x + e4.z * w2.x + e4.w * w3.x;
            s1 += e4.x * w0.y + e4.y * w1.y + e4.z * w2.y + e4.w * w3.y;
        }
        float m = s_mask[r];
        float v0 = (m == 0.f) ? -1e20f : (s0 + bea[q * 2]);
        float v1 = (m == 0.f) ? -1e20f : (s1 + bea[q * 2 + 1]);
        int ni = s_i[r], nj = s_j[r];
        float* Ab0 = g_att + (size_t)(b * 8 + q * 2) * 16384;
        float* Ab1 = Ab0 + 16384;
        Ab0[ni * 128 + nj] = v0;
        Ab0[nj * 128 + ni] = v0;
        Ab1[ni * 128 + nj] = v1;
        Ab1[nj * 128 + ni] = v1;
    }
}

// ---------------------------------------------------------------------------
// K4: fused logits + softmax + P@V.  NEW: grid = 512 (b, h, n-eighth of 16
// rows), block = 256 — doubles blocks/SM (smem 40KB -> ~29KB) for latency
// hiding.  Warp = 2 query rows; lane = 4 keys.
// ---------------------------------------------------------------------------
__global__ void k_lsm() {
    int bx = blockIdx.x;
    int b = bx >> 6, h = (bx >> 3) & 7, nq = bx & 7;
    int n0 = nq * 16;
    __shared__ float Qs[16 * 36];
    __shared__ float KV[128 * 36];   // first Ks_t[k*132+m], then Vs[m*36+d]
    __shared__ float Ps[16 * 132];
    int t = threadIdx.x;

    if (t < 128) {   // Q rows n0..n0+15 : one float4 per thread
        int n = t >> 3, f = t & 7;
        float4 q = *(const float4*)&g_qkv[(size_t)(b * 128 + n0 + n) * 768 + h * 32 + f * 4];
        *(float4*)&Qs[n * 36 + f * 4] = q;
    }
    #pragma unroll
    for (int i = t; i < 1024; i += 256) {   // K transposed store
        int m = i >> 3, f = i & 7;
        float4 kk = *(const float4*)&g_qkv[(size_t)(b * 128 + m) * 768 + 256 + h * 32 + f * 4];
        KV[(f * 4 + 0) * 132 + m] = kk.x;
        KV[(f * 4 + 1) * 132 + m] = kk.y;
        KV[(f * 4 + 2) * 132 + m] = kk.z;
        KV[(f * 4 + 3) * 132 + m] = kk.w;
    }
    __syncthreads();

    int n_g = t >> 5;   // warp id = query-row pair (2 rows)
    int m_g = t & 31;   // lane = key group (4 keys)
    ull acc2[2][2];
    #pragma unroll
    for (int i = 0; i < 2; i++) { acc2[i][0] = 0ULL; acc2[i][1] = 0ULL; }

    #pragma unroll 8
    for (int k = 0; k < 32; k++) {
        ulonglong2 kv = *(const ulonglong2*)&KV[k * 132 + m_g * 4];
        #pragma unroll
        for (int i = 0; i < 2; i++) {
            float q = Qs[(n_g * 2 + i) * 36 + k];
            ull qp = pk2(q, q);
            fma2(acc2[i][0], qp, kv.x);
            fma2(acc2[i][1], qp, kv.y);
        }
    }

    const float scale = 0.17677669529663687f;  // 1/sqrt(32)
    float* Lb = g_att + (size_t)(b * 8 + h) * 16384;
    #pragma unroll
    for (int i = 0; i < 2; i++) {
        int n = n0 + n_g * 2 + i;
        float2 a01 = upk2(acc2[i][0]), a23 = upk2(acc2[i][1]);
        float4 adj = *(const float4*)&Lb[n * 128 + m_g * 4];
        float lg[4];
        lg[0] = (n == m_g * 4 + 0) ? -1e20f : fmaf(a01.x, scale, adj.x);
        lg[1] = (n == m_g * 4 + 1) ? -1e20f : fmaf(a01.y, scale, adj.y);
        lg[2] = (n == m_g * 4 + 2) ? -1e20f : fmaf(a23.x, scale, adj.z);
        lg[3] = (n == m_g * 4 + 3) ? -1e20f : fmaf(a23.y, scale, adj.w);
        float mx = fmaxf(fmaxf(lg[0], lg[1]), fmaxf(lg[2], lg[3]));
        #pragma unroll
        for (int o = 16; o; o >>= 1) mx = fmaxf(mx, __shfl_xor_sync(0xFFFFFFFFu, mx, o));
        float anyv = (mx > -1e19f) ? 1.f : 0.f;
        float e0 = __expf(lg[0] - mx), e1 = __expf(lg[1] - mx);
        float e2 = __expf(lg[2] - mx), e3 = __expf(lg[3] - mx);
        float sum = e0 + e1 + e2 + e3;
        #pragma unroll
        for (int o = 16; o; o >>= 1) sum += __shfl_xor_sync(0xFFFFFFFFu, sum, o);
        float inv = anyv / sum;
        float4 p = make_float4(e0 * inv, e1 * inv, e2 * inv, e3 * inv);
        *(float4*)&Ps[(n_g * 2 + i) * 132 + m_g * 4] = p;
        *(float4*)&Lb[n * 128 + m_g * 4] = p;
        if (m_g == 0) g_anyv[b * 128 + n] = anyv;
    }
    __syncthreads();

    // stage V into KV (natural layout [m][36])
    #pragma unroll
    for (int i = t; i < 1024; i += 256) {
        int m = i >> 3, f = i & 7;
        float4 v = *(const float4*)&g_qkv[(size_t)(b * 128 + m) * 768 + 512 + h * 32 + f * 4];
        *(float4*)&KV[m * 36 + f * 4] = v;
    }
    __syncthreads();

    // P @ V : thread = (row group ng2 0..7, dim d); 2 rows each
    {
        int d = t & 31, ng2 = t >> 5;
        float a0 = 0.f, a1 = 0.f;
        #pragma unroll 4
        for (int m = 0; m < 128; m++) {
            float v = KV[m * 36 + d];
            a0 += Ps[ng2 * 132 + m] * v;
            a1 += Ps[(ng2 + 8) * 132 + m] * v;
        }
        g_attn[(size_t)(b * 128 + n0 + ng2) * 256 + h * 32 + d] = a0;
        g_attn[(size_t)(b * 128 + n0 + ng2 + 8) * 256 + h * 32 + d] = a1;
    }
}

// ---------------------------------------------------------------------------
// K5: MERGED e_in aggregation + Wev projection.  [R12 — unchanged]
// grid = 1024 (one (b,n)), block = 256.
// ---------------------------------------------------------------------------
__global__ void k_aggp(const float* __restrict__ Wev, const float* __restrict__ bev) {
    int bx = blockIdx.x;
    int b = bx >> 7, n = bx & 127;
    int t = threadIdx.x;

    __shared__ float ps[8 * 128];
    __shared__ int pidx_s[128];
    __shared__ float psum[2 * 8 * 128];
    __shared__ float aE[8 * 128];

    if (t < 128) pidx_s[t] = (t == n) ? 0 : pair_idx(n, t);
    {
        int hh = t >> 5, mg = t & 31;
        const float* Lb = g_att + ((size_t)(b * 8 + hh) * 128 + n) * 128;
        *(float4*)&ps[hh * 128 + mg * 4] = *(const float4*)&Lb[mg * 4];
    }
    __syncthreads();

    int cg = t & 31;
    int g2 = t >> 5;
    int hp = (g2 & 3) * 2;
    int ms = g2 >> 2;
    int pbase = b * PP;
    float4 a0 = make_float4(0.f, 0.f, 0.f, 0.f);
    float4 a1 = make_float4(0.f, 0.f, 0.f, 0.f);
    int mbeg = ms * 64;
    #pragma unroll 4
    for (int mm = 0; mm < 64; mm++) {
        int m = mbeg + mm;
        const float4 ev = *(const float4*)&g_e_in[(size_t)(pbase + pidx_s[m]) * 128 + cg * 4];
        float p0 = ps[hp * 128 + m];
        float p1 = ps[(hp + 1) * 128 + m];
        a0.x += p0 * ev.x; a0.y += p0 * ev.y; a0.z += p0 * ev.z; a0.w += p0 * ev.w;
        a1.x += p1 * ev.x; a1.y += p1 * ev.y; a1.z += p1 * ev.z; a1.w += p1 * ev.w;
    }
    *(float4*)&psum[(ms * 8 + hp) * 128 + cg * 4] = a0;
    *(float4*)&psum[(ms * 8 + hp + 1) * 128 + cg * 4] = a1;
    __syncthreads();

    {   // reduce the 2 m-splits into aE
        int hh = t >> 5, cc = t & 31;
        float4 r0 = *(float4*)&psum[(hh * 128) + cc * 4];
        float4 r1 = *(float4*)&psum[((8 + hh) * 128) + cc * 4];
        float4 o;
        o.x = r0.x + r1.x; o.y = r0.y + r1.y; o.z = r0.z + r1.z; o.w = r0.w + r1.w;
        *(float4*)&aE[hh * 128 + cc * 4] = o;
    }
    __syncthreads();

    // Phase 2: projection.  t = output column = h*32+d.
    {
        int h = t >> 5;
        const float* row = &aE[h * 128];
        float acc = 0.f;
        #pragma unroll 8
        for (int c = 0; c < 128; c++) acc += row[c] * Wev[c * 256 + t];
        float any = g_anyv[bx];
        g_attn[(size_t)bx * 256 + t] += acc + any * bev[t];
    }
}

// ---------------------------------------------------------------------------
// K6: fused output.  [EXACT R8/R12 version — grid 256, 4 rows/block]
// ---------------------------------------------------------------------------
__global__ void k_out(const float* __restrict__ Wo, const float* __restrict__ bo,
                      const float* __restrict__ Wsk, const float* __restrict__ bsk,
                      const float* __restrict__ nf, float* __restrict__ out) {
    __shared__ float cs[4 * 512];
    __shared__ float comb[4 * 256];
    __shared__ float vg[4 * 512];
    int row0 = blockIdx.x * 4;
    int t = threadIdx.x;
    #pragma unroll
    for (int i = t; i < 512; i += 256) {
        int r = i >> 7, f = i & 127;
        float4 v = (f < 64)
            ? *(const float4*)&g_n_in[(size_t)(row0 + r) * 256 + f * 4]
            : *(const float4*)&g_attn[(size_t)(row0 + r) * 256 + (f - 64) * 4];
        *(float4*)&cs[r * 512 + f * 4] = v;
    }
    __syncthreads();

    // GEMM1: 4 rows x 256 cols; thread = (row rg, 4 cols)
    {
        int cg = t & 63, rg = t >> 6;
        float4 acc = make_float4(0.f, 0.f, 0.f, 0.f);
        for (int k = 0; k < 512; k++) {
            float4 w = *(const float4*)&Wo[k * 256 + cg * 4];
            float a = cs[rg * 512 + k];
            acc.x += a * w.x; acc.y += a * w.y; acc.z += a * w.z; acc.w += a * w.w;
        }
        float4 bb = *(const float4*)&bo[cg * 4];
        const float is2 = 0.70710678118654752f;
        float x;
        float4 o;
        x = acc.x + bb.x; o.x = 0.5f * x * (1.f + erff(x * is2));
        x = acc.y + bb.y; o.y = 0.5f * x * (1.f + erff(x * is2));
        x = acc.z + bb.z; o.z = 0.5f * x * (1.f + erff(x * is2));
        x = acc.w + bb.w; o.w = 0.5f * x * (1.f + erff(x * is2));
        *(float4*)&comb[rg * 256 + cg * 4] = o;
    }
    __syncthreads();

    // GEMM2: 4 rows x 512 cols; thread = (2 rows, 4 cols)
    {
        int cg = t & 127, rg = t >> 7;
        float4 acc0 = make_float4(0.f, 0.f, 0.f, 0.f);
        float4 acc1 = make_float4(0.f, 0.f, 0.f, 0.f);
        for (int k = 0; k < 256; k++) {
            float4 w = *(const float4*)&Wsk[k * 512 + cg * 4];
            float a0 = comb[(rg * 2) * 256 + k];
            float a1 = comb[(rg * 2 + 1) * 256 + k];
            acc0.x += a0 * w.x; acc0.y += a0 * w.y; acc0.z += a0 * w.z; acc0.w += a0 * w.w;
            acc1.x += a1 * w.x; acc1.y += a1 * w.y; acc1.z += a1 * w.z; acc1.w += a1 * w.w;
        }
        float4 bb = *(const float4*)&bsk[cg * 4];
        float4 o0, o1;
        o0.x = acc0.x + bb.x; o0.y = acc0.y + bb.y; o0.z = acc0.z + bb.z; o0.w = acc0.w + bb.w;
        o1.x = acc1.x + bb.x; o1.y = acc1.y + bb.y; o1.z = acc1.z + bb.z; o1.w = acc1.w + bb.w;
        *(float4*)&vg[(rg * 2) * 512 + cg * 4] = o0;
        *(float4*)&vg[(rg * 2 + 1) * 512 + cg * 4] = o1;
    }
    __syncthreads();

    #pragma unroll
    for (int r = 0; r < 4; r++) {
        float val  = vg[r * 512 + t];
        float gate = vg[r * 512 + 256 + t];
        float g = 1.0f / (1.0f + __expf(-gate));
        size_t idx = (size_t)(row0 + r) * 256 + t;
        out[idx] = nf[idx] * (1.0f - g) + val * g;
    }
}

// ---------------------------------------------------------------------------
extern "C" void kernel_launch(void* const* d_in, const int* in_sizes, int n_in,
                              void* d_out, int out_size) {
    const float* node_feat = (const float*)d_in[0];
    const float* edge_feat = (const float*)d_in[1];
    const int* x_idx1 = (const int*)d_in[2];
    const int* x_idx2 = (const int*)d_in[3];
    const float* mask_valid = (const float*)d_in[4];
    const float* Wqkv = (const float*)d_in[5];
    const float* bqkv = (const float*)d_in[6];
    const float* Wev  = (const float*)d_in[7];
    const float* bev  = (const float*)d_in[8];
    const float* Wea  = (const float*)d_in[9];
    const float* bea  = (const float*)d_in[10];
    const float* Wo   = (const float*)d_in[11];
    const float* bo   = (const float*)d_in[12];
    const float* Wsk  = (const float*)d_in[13];
    const float* bsk  = (const float*)d_in[14];
    const float* gn   = (const float*)d_in[15];
    const float* bn   = (const float*)d_in[16];
    const float* ge   = (const float*)d_in[17];
    const float* be   = (const float*)d_in[18];
    float* out = (float*)d_out;

    k_qkv<<<dim3(64, 3), 256>>>(node_feat, gn, bn, Wqkv, bqkv);
    k_edge<<<1016, 256>>>(edge_feat, ge, be, Wea, bea, x_idx1, x_idx2, mask_valid);
    k_lsm<<<512, 256>>>();
    k_aggp<<<1024, 256>>>(Wev, bev);
    k_out<<<256, 256>>>(Wo, bo, Wsk, bsk, node_feat, out);
}

// round 17
// speedup vs baseline: 1.1668x; 1.1668x over previous
#include <cuda_runtime.h>
#include <math.h>

// Problem constants
#define BB 8
#define NN 128
#define HN_ 256
#define HE_ 128
#define NH 8
#define DH_ 32
#define PP 8128
#define BP 65024   // B * P

typedef unsigned long long ull;

__device__ __forceinline__ ull pk2(float x, float y) {
    ull r; asm("mov.b64 %0,{%1,%2};" : "=l"(r) : "f"(x), "f"(y)); return r;
}
__device__ __forceinline__ float2 upk2(ull v) {
    float2 f; asm("mov.b64 {%0,%1},%2;" : "=f"(f.x), "=f"(f.y) : "l"(v)); return f;
}
// d = a*b + d  (packed f32x2 FFMA) — only where operands are pre-packed (k_lsm)
__device__ __forceinline__ void fma2(ull& d, ull a, ull b) {
    asm("fma.rn.f32x2 %0,%1,%2,%0;" : "+l"(d) : "l"(a), "l"(b));
}

// Scratch (no cudaMalloc allowed -> __device__ globals)
__device__ float g_n_in[1024 * 256];     // [B*N, HN]
__device__ float g_qkv[1024 * 768];      // [B*N, 3*HN]
__device__ float g_e_in[BP * 128];       // [B*P, HE]
__device__ float g_att[64 * 128 * 128];  // [B*H, N, N] adj -> probs (in place)
__device__ float g_anyv[1024];           // [B*N]
__device__ float g_attn[1024 * 256];     // [B*N, HN]

__device__ __forceinline__ int pair_idx(int i, int j) {
    if (i > j) { int t = i; i = j; j = t; }
    return i * (255 - i) / 2 + (j - i - 1);
}

// ---------------------------------------------------------------------------
// K1: node LayerNorm.  grid = 1024, block = 256   [R12]
// ---------------------------------------------------------------------------
__global__ void k_node_ln(const float* __restrict__ nf,
                          const float* __restrict__ gn,
                          const float* __restrict__ bn) {
    int row = blockIdx.x;
    int t = threadIdx.x;
    float x = nf[row * 256 + t];
    float s = x, s2 = x * x;
    #pragma unroll
    for (int o = 16; o; o >>= 1) {
        s  += __shfl_xor_sync(0xFFFFFFFFu, s,  o);
        s2 += __shfl_xor_sync(0xFFFFFFFFu, s2, o);
    }
    __shared__ float rs_[8], rs2_[8];
    int w = t >> 5, l = t & 31;
    if (l == 0) { rs_[w] = s; rs2_[w] = s2; }
    __syncthreads();
    float tot = 0.f, tot2 = 0.f;
    #pragma unroll
    for (int i = 0; i < 8; i++) { tot += rs_[i]; tot2 += rs2_[i]; }
    float mean = tot * (1.0f / 256.0f);
    float var  = tot2 * (1.0f / 256.0f) - mean * mean;
    float rstd = rsqrtf(var + 1e-5f);
    g_n_in[row * 256 + t] = (x - mean) * rstd * gn[t] + bn[t];
}

// ---------------------------------------------------------------------------
// K2: qkv GEMM. grid=(64,3), block=256.  [R12 scalar]
// ---------------------------------------------------------------------------
__global__ void k_qkv(const float* __restrict__ W, const float* __restrict__ bias) {
    __shared__ float As[16 * 256];
    int t = threadIdx.x;
    int row0 = blockIdx.x * 16;
    int cb = blockIdx.y * 256;
    const float4* a4 = (const float4*)(g_n_in + row0 * 256);
    float4* s4 = (float4*)As;
    #pragma unroll
    for (int i = t; i < 1024; i += 256) s4[i] = a4[i];
    __syncthreads();
    int cg = t & 63;
    int rg = t >> 6;
    float4 acc[4];
    #pragma unroll
    for (int r = 0; r < 4; r++) acc[r] = make_float4(0.f, 0.f, 0.f, 0.f);
    for (int k = 0; k < 256; k++) {
        float4 w = *(const float4*)&W[k * 768 + cb + cg * 4];
        #pragma unroll
        for (int r = 0; r < 4; r++) {
            float a = As[(rg * 4 + r) * 256 + k];
            acc[r].x += a * w.x; acc[r].y += a * w.y;
            acc[r].z += a * w.z; acc[r].w += a * w.w;
        }
    }
    float4 bb = *(const float4*)&bias[cb + cg * 4];
    #pragma unroll
    for (int r = 0; r < 4; r++) {
        float4 o;
        o.x = acc[r].x + bb.x; o.y = acc[r].y + bb.y;
        o.z = acc[r].z + bb.z; o.w = acc[r].w + bb.w;
        *(float4*)&g_qkv[(row0 + rg * 4 + r) * 768 + cb + cg * 4] = o;
    }
}

// ---------------------------------------------------------------------------
// K3: edge LayerNorm + e_adj scatter into g_att.  [R12]
// grid = 1016 (64 edge rows per block), block = 256.
// ---------------------------------------------------------------------------
__global__ void k_edge(const float* __restrict__ ef,
                       const float* __restrict__ ge, const float* __restrict__ be,
                       const float* __restrict__ Wea, const float* __restrict__ bea,
                       const int* __restrict__ i1, const int* __restrict__ i2,
                       const float* __restrict__ mask) {
    __shared__ float es[64 * 132];
    __shared__ float wa[128 * 8];
    __shared__ float ges[128], bes[128];
    __shared__ int s_i[64], s_j[64];
    __shared__ float s_mask[64];
    int t = threadIdx.x;
    int base_row = blockIdx.x * 64;
    int b = base_row / 8128;
    int p0 = base_row - b * 8128;
    int base = base_row * 128;

    float4* es4 = (float4*)es;
    const float4* ef4 = (const float4*)(ef + base);
    #pragma unroll
    for (int i = t; i < 2048; i += 256) es4[(i >> 5) * 33 + (i & 31)] = ef4[i];
    for (int i = t; i < 1024; i += 256) wa[i] = Wea[i];
    if (t < 128) { ges[t] = ge[t]; bes[t] = be[t]; }
    if (t < 64) {
        int p = p0 + t;
        s_i[t] = i1[p]; s_j[t] = i2[p];
        s_mask[t] = mask[b * PP + p];
    }
    __syncthreads();

    int w = t >> 5, l = t & 31;
    #pragma unroll
    for (int rr = 0; rr < 8; rr++) {
        int r = w * 8 + rr;
        float4 v = *(float4*)&es[r * 132 + l * 4];
        float s  = v.x + v.y + v.z + v.w;
        float s2 = v.x * v.x + v.y * v.y + v.z * v.z + v.w * v.w;
        #pragma unroll
        for (int o = 16; o; o >>= 1) {
            s  += __shfl_xor_sync(0xFFFFFFFFu, s,  o);
            s2 += __shfl_xor_sync(0xFFFFFFFFu, s2, o);
        }
        float mean = s * (1.0f / 128.0f);
        float var  = s2 * (1.0f / 128.0f) - mean * mean;
        float rstd = rsqrtf(var + 1e-5f);
        int c = l * 4;
        float4 o4;
        o4.x = (v.x - mean) * rstd * ges[c + 0] + bes[c + 0];
        o4.y = (v.y - mean) * rstd * ges[c + 1] + bes[c + 1];
        o4.z = (v.z - mean) * rstd * ges[c + 2] + bes[c + 2];
        o4.w = (v.w - mean) * rstd * ges[c + 3] + bes[c + 3];
        *(float4*)&es[r * 132 + c] = o4;
    }
    __syncthreads();

    float4* out4 = (float4*)(g_e_in + base);
    #pragma unroll
    for (int i = t; i < 2048; i += 256) out4[i] = es4[(i >> 5) * 33 + (i & 31)];

    {
        int r = t >> 2, q = t & 3;
        float s0 = 0.f, s1 = 0.f;
        #pragma unroll 8
        for (int c4 = 0; c4 < 32; c4++) {
            float4 e4 = *(float4*)&es[r * 132 + c4 * 4];
            int c = c4 * 4;
            float2 w0 = *(float2*)&wa[(c + 0) * 8 + q * 2];
            float2 w1 = *(float2*)&wa[(c + 1) * 8 + q * 2];
            float2 w2 = *(float2*)&wa[(c + 2) * 8 + q * 2];
            float2 w3 = *(float2*)&wa[(c + 3) * 8 + q * 2];
            s0 += e4.x * w0.x + e4.y * w1.x + e4.z * w2.x + e4.w * w3.x;
            s1 += e4.x * w0.y + e4.y * w1.y + e4.z * w2.y + e4.w * w3.y;
        }
        float m = s_mask[r];
        float v0 = (m == 0.f) ? -1e20f : (s0 + bea[q * 2]);
        float v1 = (m == 0.f) ? -1e20f : (s1 + bea[q * 2 + 1]);
        int ni = s_i[r], nj = s_j[r];
        float* Ab0 = g_att + (size_t)(b * 8 + q * 2) * 16384;
        float* Ab1 = Ab0 + 16384;
        Ab0[ni * 128 + nj] = v0;
        Ab0[nj * 128 + ni] = v0;
        Ab1[ni * 128 + nj] = v1;
        Ab1[nj * 128 + ni] = v1;
    }
}

// ---------------------------------------------------------------------------
// K4: fused logits + softmax + P@V.  [R9/R12 — grid 256, measured best]
// ---------------------------------------------------------------------------
__global__ void k_lsm() {
    int bx = blockIdx.x;
    int b = bx >> 5, h = (bx >> 2) & 7, nq = bx & 3;
    int n0 = nq * 32;
    __shared__ float Qs[32 * 36];
    __shared__ float KV[128 * 36];
    __shared__ float Ps[32 * 132];
    int t = threadIdx.x;

    {
        int n = t >> 3, f = t & 7;
        float4 q = *(const float4*)&g_qkv[(size_t)(b * 128 + n0 + n) * 768 + h * 32 + f * 4];
        *(float4*)&Qs[n * 36 + f * 4] = q;
    }
    #pragma unroll
    for (int i = t; i < 1024; i += 256) {
        int m = i >> 3, f = i & 7;
        float4 kk = *(const float4*)&g_qkv[(size_t)(b * 128 + m) * 768 + 256 + h * 32 + f * 4];
        KV[(f * 4 + 0) * 132 + m] = kk.x;
        KV[(f * 4 + 1) * 132 + m] = kk.y;
        KV[(f * 4 + 2) * 132 + m] = kk.z;
        KV[(f * 4 + 3) * 132 + m] = kk.w;
    }
    __syncthreads();

    int n_g = t >> 5;
    int m_g = t & 31;
    ull acc2[4][2];
    #pragma unroll
    for (int i = 0; i < 4; i++) { acc2[i][0] = 0ULL; acc2[i][1] = 0ULL; }

    #pragma unroll 8
    for (int k = 0; k < 32; k++) {
        ulonglong2 kv = *(const ulonglong2*)&KV[k * 132 + m_g * 4];
        #pragma unroll
        for (int i = 0; i < 4; i++) {
            float q = Qs[(n_g * 4 + i) * 36 + k];
            ull qp = pk2(q, q);
            fma2(acc2[i][0], qp, kv.x);
            fma2(acc2[i][1], qp, kv.y);
        }
    }

    const float scale = 0.17677669529663687f;
    float* Lb = g_att + (size_t)(b * 8 + h) * 16384;
    #pragma unroll
    for (int i = 0; i < 4; i++) {
        int n = n0 + n_g * 4 + i;
        float2 a01 = upk2(acc2[i][0]), a23 = upk2(acc2[i][1]);
        float4 adj = *(const float4*)&Lb[n * 128 + m_g * 4];
        float lg[4];
        lg[0] = (n == m_g * 4 + 0) ? -1e20f : fmaf(a01.x, scale, adj.x);
        lg[1] = (n == m_g * 4 + 1) ? -1e20f : fmaf(a01.y, scale, adj.y);
        lg[2] = (n == m_g * 4 + 2) ? -1e20f : fmaf(a23.x, scale, adj.z);
        lg[3] = (n == m_g * 4 + 3) ? -1e20f : fmaf(a23.y, scale, adj.w);
        float mx = fmaxf(fmaxf(lg[0], lg[1]), fmaxf(lg[2], lg[3]));
        #pragma unroll
        for (int o = 16; o; o >>= 1) mx = fmaxf(mx, __shfl_xor_sync(0xFFFFFFFFu, mx, o));
        float anyv = (mx > -1e19f) ? 1.f : 0.f;
        float e0 = __expf(lg[0] - mx), e1 = __expf(lg[1] - mx);
        float e2 = __expf(lg[2] - mx), e3 = __expf(lg[3] - mx);
        float sum = e0 + e1 + e2 + e3;
        #pragma unroll
        for (int o = 16; o; o >>= 1) sum += __shfl_xor_sync(0xFFFFFFFFu, sum, o);
        float inv = anyv / sum;
        float4 p = make_float4(e0 * inv, e1 * inv, e2 * inv, e3 * inv);
        *(float4*)&Ps[(n_g * 4 + i) * 132 + m_g * 4] = p;
        *(float4*)&Lb[n * 128 + m_g * 4] = p;
        if (m_g == 0) g_anyv[b * 128 + n] = anyv;
    }
    __syncthreads();

    #pragma unroll
    for (int i = t; i < 1024; i += 256) {
        int m = i >> 3, f = i & 7;
        float4 v = *(const float4*)&g_qkv[(size_t)(b * 128 + m) * 768 + 512 + h * 32 + f * 4];
        *(float4*)&KV[m * 36 + f * 4] = v;
    }
    __syncthreads();

    {
        int d = t & 31, ng2 = t >> 5;
        float a2[4];
        #pragma unroll
        for (int j = 0; j < 4; j++) a2[j] = 0.f;
        #pragma unroll 4
        for (int m = 0; m < 128; m++) {
            float v = KV[m * 36 + d];
            #pragma unroll
            for (int j = 0; j < 4; j++) a2[j] += Ps[(ng2 + 8 * j) * 132 + m] * v;
        }
        #pragma unroll
        for (int j = 0; j < 4; j++) {
            int n = n0 + ng2 + 8 * j;
            g_attn[(size_t)(b * 128 + n) * 256 + h * 32 + d] = a2[j];
        }
    }
}

// ---------------------------------------------------------------------------
// K5: MERGED e_in aggregation + Wev projection.  NEW inner structure.
// grid = 1024 (one (b,n)), block = 256.
// Probs stored TRANSPOSED ps_t[m][16-padded]; thread = (col-float4 cg,
// head-quad hg, 4-way m-split ms): per iter 1 coalesced LDG.128 (e_in) +
// 1 broadcast LDS.128 (4 probs) + 16 FMA.  e_in L1 redundancy 4x -> 2x,
// LDS count /4, FMA density 2x.
// ---------------------------------------------------------------------------
__global__ void k_aggp(const float* __restrict__ Wev, const float* __restrict__ bev) {
    int bx = blockIdx.x;
    int b = bx >> 7, n = bx & 127;
    int t = threadIdx.x;

    __shared__ float ps_t[128 * 16];   // [m][h], padded row 16 -> 8KB
    __shared__ int pidx_s[128];
    __shared__ float psum[32 * 128];   // [ms*8 + h][128] -> 16KB
    __shared__ float aE[8 * 128];      // 4KB

    if (t < 128) pidx_s[t] = (t == n) ? 0 : pair_idx(n, t);
    {   // load probs transposed: thread (hh = t&7, mg = t>>3)
        int hh = t & 7, mg = t >> 3;
        const float* Lb = g_att + ((size_t)(b * 8 + hh) * 128 + n) * 128;
        float4 p = *(const float4*)&Lb[mg * 4];
        ps_t[(mg * 4 + 0) * 16 + hh] = p.x;
        ps_t[(mg * 4 + 1) * 16 + hh] = p.y;
        ps_t[(mg * 4 + 2) * 16 + hh] = p.z;
        ps_t[(mg * 4 + 3) * 16 + hh] = p.w;
    }
    __syncthreads();

    int cg = t & 31;          // column float4 (cols cg*4..cg*4+3)
    int hg = (t >> 5) & 1;    // head quad: heads hg*4..hg*4+3
    int ms = t >> 6;          // m-split 0..3 (32 m each)
    int pbase = b * PP;
    float4 a0 = make_float4(0.f, 0.f, 0.f, 0.f);
    float4 a1 = make_float4(0.f, 0.f, 0.f, 0.f);
    float4 a2 = make_float4(0.f, 0.f, 0.f, 0.f);
    float4 a3 = make_float4(0.f, 0.f, 0.f, 0.f);
    int mbeg = ms * 32;
    #pragma unroll 4
    for (int mm = 0; mm < 32; mm++) {
        int m = mbeg + mm;
        float4 ev = *(const float4*)&g_e_in[(size_t)(pbase + pidx_s[m]) * 128 + cg * 4];
        float4 p4 = *(const float4*)&ps_t[m * 16 + hg * 4];
        a0.x += p4.x * ev.x; a0.y += p4.x * ev.y; a0.z += p4.x * ev.z; a0.w += p4.x * ev.w;
        a1.x += p4.y * ev.x; a1.y += p4.y * ev.y; a1.z += p4.y * ev.z; a1.w += p4.y * ev.w;
        a2.x += p4.z * ev.x; a2.y += p4.z * ev.y; a2.z += p4.z * ev.z; a2.w += p4.z * ev.w;
        a3.x += p4.w * ev.x; a3.y += p4.w * ev.y; a3.z += p4.w * ev.z; a3.w += p4.w * ev.w;
    }
    int hbase = ms * 8 + hg * 4;
    *(float4*)&psum[(hbase + 0) * 128 + cg * 4] = a0;
    *(float4*)&psum[(hbase + 1) * 128 + cg * 4] = a1;
    *(float4*)&psum[(hbase + 2) * 128 + cg * 4] = a2;
    *(float4*)&psum[(hbase + 3) * 128 + cg * 4] = a3;
    __syncthreads();

    {   // reduce the 4 m-splits into aE
        int hh = t >> 5, cc = t & 31;
        float4 o = make_float4(0.f, 0.f, 0.f, 0.f);
        #pragma unroll
        for (int s = 0; s < 4; s++) {
            float4 r = *(float4*)&psum[(s * 8 + hh) * 128 + cc * 4];
            o.x += r.x; o.y += r.y; o.z += r.z; o.w += r.w;
        }
        *(float4*)&aE[hh * 128 + cc * 4] = o;
    }
    __syncthreads();

    // Phase 2: projection.  t = output column = h*32+d.
    {
        int h = t >> 5;
        const float* row = &aE[h * 128];
        float acc = 0.f;
        #pragma unroll 8
        for (int c = 0; c < 128; c++) acc += row[c] * Wev[c * 256 + t];
        float any = g_anyv[bx];
        g_attn[(size_t)bx * 256 + t] += acc + any * bev[t];
    }
}

// ---------------------------------------------------------------------------
// K6: fused output.  [R8/R12 — grid 256, 4 rows/block]
// ---------------------------------------------------------------------------
__global__ void k_out(const float* __restrict__ Wo, const float* __restrict__ bo,
                      const float* __restrict__ Wsk, const float* __restrict__ bsk,
                      const float* __restrict__ nf, float* __restrict__ out) {
    __shared__ float cs[4 * 512];
    __shared__ float comb[4 * 256];
    __shared__ float vg[4 * 512];
    int row0 = blockIdx.x * 4;
    int t = threadIdx.x;
    #pragma unroll
    for (int i = t; i < 512; i += 256) {
        int r = i >> 7, f = i & 127;
        float4 v = (f < 64)
            ? *(const float4*)&g_n_in[(size_t)(row0 + r) * 256 + f * 4]
            : *(const float4*)&g_attn[(size_t)(row0 + r) * 256 + (f - 64) * 4];
        *(float4*)&cs[r * 512 + f * 4] = v;
    }
    __syncthreads();

    // GEMM1: 4 rows x 256 cols; thread = (row rg, 4 cols)
    {
        int cg = t & 63, rg = t >> 6;
        float4 acc = make_float4(0.f, 0.f, 0.f, 0.f);
        for (int k = 0; k < 512; k++) {
            float4 w = *(const float4*)&Wo[k * 256 + cg * 4];
            float a = cs[rg * 512 + k];
            acc.x += a * w.x; acc.y += a * w.y; acc.z += a * w.z; acc.w += a * w.w;
        }
        float4 bb = *(const float4*)&bo[cg * 4];
        const float is2 = 0.70710678118654752f;
        float x;
        float4 o;
        x = acc.x + bb.x; o.x = 0.5f * x * (1.f + erff(x * is2));
        x = acc.y + bb.y; o.y = 0.5f * x * (1.f + erff(x * is2));
        x = acc.z + bb.z; o.z = 0.5f * x * (1.f + erff(x * is2));
        x = acc.w + bb.w; o.w = 0.5f * x * (1.f + erff(x * is2));
        *(float4*)&comb[rg * 256 + cg * 4] = o;
    }
    __syncthreads();

    // GEMM2: 4 rows x 512 cols; thread = (2 rows, 4 cols)
    {
        int cg = t & 127, rg = t >> 7;
        float4 acc0 = make_float4(0.f, 0.f, 0.f, 0.f);
        float4 acc1 = make_float4(0.f, 0.f, 0.f, 0.f);
        for (int k = 0; k < 256; k++) {
            float4 w = *(const float4*)&Wsk[k * 512 + cg * 4];
            float a0 = comb[(rg * 2) * 256 + k];
            float a1 = comb[(rg * 2 + 1) * 256 + k];
            acc0.x += a0 * w.x; acc0.y += a0 * w.y; acc0.z += a0 * w.z; acc0.w += a0 * w.w;
            acc1.x += a1 * w.x; acc1.y += a1 * w.y; acc1.z += a1 * w.z; acc1.w += a1 * w.w;
        }
        float4 bb = *(const float4*)&bsk[cg * 4];
        float4 o0, o1;
        o0.x = acc0.x + bb.x; o0.y = acc0.y + bb.y; o0.z = acc0.z + bb.z; o0.w = acc0.w + bb.w;
        o1.x = acc1.x + bb.x; o1.y = acc1.y + bb.y; o1.z = acc1.z + bb.z; o1.w = acc1.w + bb.w;
        *(float4*)&vg[(rg * 2) * 512 + cg * 4] = o0;
        *(float4*)&vg[(rg * 2 + 1) * 512 + cg * 4] = o1;
    }
    __syncthreads();

    #pragma unroll
    for (int r = 0; r < 4; r++) {
        float val  = vg[r * 512 + t];
        float gate = vg[r * 512 + 256 + t];
        float g = 1.0f / (1.0f + __expf(-gate));
        size_t idx = (size_t)(row0 + r) * 256 + t;
        out[idx] = nf[idx] * (1.0f - g) + val * g;
    }
}

// ---------------------------------------------------------------------------
extern "C" void kernel_launch(void* const* d_in, const int* in_sizes, int n_in,
                              void* d_out, int out_size) {
    const float* node_feat = (const float*)d_in[0];
    const float* edge_feat = (const float*)d_in[1];
    const int* x_idx1 = (const int*)d_in[2];
    const int* x_idx2 = (const int*)d_in[3];
    const float* mask_valid = (const float*)d_in[4];
    const float* Wqkv = (const float*)d_in[5];
    const float* bqkv = (const float*)d_in[6];
    const float* Wev  = (const float*)d_in[7];
    const float* bev  = (const float*)d_in[8];
    const float* Wea  = (const float*)d_in[9];
    const float* bea  = (const float*)d_in[10];
    const float* Wo   = (const float*)d_in[11];
    const float* bo   = (const float*)d_in[12];
    const float* Wsk  = (const float*)d_in[13];
    const float* bsk  = (const float*)d_in[14];
    const float* gn   = (const float*)d_in[15];
    const float* bn   = (const float*)d_in[16];
    const float* ge   = (const float*)d_in[17];
    const float* be   = (const float*)d_in[18];
    float* out = (float*)d_out;

    k_node_ln<<<1024, 256>>>(node_feat, gn, bn);
    k_qkv<<<dim3(64, 3), 256>>>(Wqkv, bqkv);
    k_edge<<<1016, 256>>>(edge_feat, ge, be, Wea, bea, x_idx1, x_idx2, mask_valid);
    k_lsm<<<256, 256>>>();
    k_aggp<<<1024, 256>>>(Wev, bev);
    k_out<<<256, 256>>>(Wo, bo, Wsk, bsk, node_feat, out);
}